// round 13
// baseline (speedup 1.0000x reference)
#include <cuda_runtime.h>
#include <cuda_fp16.h>
#include <cstdint>

#define K_DIM 512
#define N_DIM 512
#define BN_EPS 1e-3f
#define KC 64
#define NKT 8              // 512/64 k-chunks
#define PITCH 144          // smem row pitch bytes (64 fp16 = 128B + 16B pad)
#define A_OFF 0
#define B_OFF 18432        // A: 128 rows * 144B
#define STAGE_SZ 55296     // + B: 256 rows * 144B
#define SMEM_TOTAL (2 * STAGE_SZ)

// precomputed W (fp16), transposed to [n][k]
__device__ __align__(16) __half g_Wt[N_DIM * K_DIM];
// per-rowblock rendezvous counters (zero at start; self-reset via CAS each run)
__device__ int g_ctr[512];

// ---------------- helpers ---------------------------------------------------
__device__ __forceinline__ uint32_t smem_u32(const void* p) {
    uint32_t a;
    asm("{ .reg .u64 t; cvta.to.shared.u64 t, %1; cvt.u32.u64 %0, t; }" : "=r"(a) : "l"(p));
    return a;
}
__device__ __forceinline__ void cp16(uint32_t dst, const void* src) {
    asm volatile("cp.async.cg.shared.global [%0], [%1], 16;" :: "r"(dst), "l"(src));
}
#define CP_COMMIT() asm volatile("cp.async.commit_group;" ::: "memory")
#define CP_WAIT0()  asm volatile("cp.async.wait_group 0;" ::: "memory")

__device__ __forceinline__ void ldsm4(uint32_t& r0, uint32_t& r1, uint32_t& r2, uint32_t& r3,
                                      uint32_t a) {
    asm volatile("ldmatrix.sync.aligned.m8n8.x4.shared.b16 {%0,%1,%2,%3}, [%4];"
                 : "=r"(r0), "=r"(r1), "=r"(r2), "=r"(r3) : "r"(a));
}
__device__ __forceinline__ void mma16816(float* d, const uint32_t* a, uint32_t b0, uint32_t b1) {
    asm volatile("mma.sync.aligned.m16n8k16.row.col.f32.f16.f16.f32 "
                 "{%0,%1,%2,%3}, {%4,%5,%6,%7}, {%8,%9}, {%0,%1,%2,%3};"
                 : "+f"(d[0]), "+f"(d[1]), "+f"(d[2]), "+f"(d[3])
                 : "r"(a[0]), "r"(a[1]), "r"(a[2]), "r"(a[3]), "r"(b0), "r"(b1));
}
__device__ __forceinline__ uint32_t pack_f16(float x, float y) {
    return (uint32_t)__half_as_ushort(__float2half_rn(x)) |
           ((uint32_t)__half_as_ushort(__float2half_rn(y)) << 16);
}

__device__ __forceinline__ float wsumf(float v) {
#pragma unroll
    for (int o = 16; o > 0; o >>= 1) v += __shfl_xor_sync(0xffffffffu, v, o);
    return v;
}
__device__ __forceinline__ int wsumi(int v) {
#pragma unroll
    for (int o = 16; o > 0; o >>= 1) v += __shfl_xor_sync(0xffffffffu, v, o);
    return v;
}

// row-wise sparsemax (Michelot fixed point), one warp, 512 elems, in-place
__device__ __forceinline__ void sparsemax_row(float* __restrict__ row, int lane) {
    float z[16];
#pragma unroll
    for (int j = 0; j < 4; ++j) {
        const float4 v = *(const float4*)&row[lane * 4 + j * 128];
        z[j * 4 + 0] = v.x; z[j * 4 + 1] = v.y; z[j * 4 + 2] = v.z; z[j * 4 + 3] = v.w;
    }
    float s = 0.f;
#pragma unroll
    for (int i = 0; i < 16; ++i) s += z[i];
    s = wsumf(s);
    int cnt = N_DIM;
    float tau = (s - 1.0f) * (1.0f / N_DIM);
#pragma unroll 1
    for (int it = 0; it < 64; ++it) {
        float s2 = 0.f; int c2 = 0;
#pragma unroll
        for (int i = 0; i < 16; ++i)
            if (z[i] > tau) { s2 += z[i]; c2++; }
        s2 = wsumf(s2);
        c2 = wsumi(c2);
        if (c2 <= 0) break;
        const float ntau = (s2 - 1.0f) / (float)c2;
        if (c2 >= cnt) { tau = ntau; break; }
        cnt = c2;
        tau = ntau;
    }
#pragma unroll
    for (int j = 0; j < 4; ++j) {
        float4 o;
        o.x = fmaxf(z[j * 4 + 0] - tau, 0.f);
        o.y = fmaxf(z[j * 4 + 1] - tau, 0.f);
        o.z = fmaxf(z[j * 4 + 2] - tau, 0.f);
        o.w = fmaxf(z[j * 4 + 3] - tau, 0.f);
        *(float4*)&row[lane * 4 + j * 128] = o;
    }
}

// ---------------- W convert/transpose ---------------------------------------
__global__ void wconv_kernel(const float* __restrict__ W) {
    int idx = blockIdx.x * 256 + threadIdx.x;   // 1024 x 256 = 512*512
    int k = idx >> 9, n = idx & 511;
    g_Wt[n * K_DIM + k] = __float2half_rn(W[idx]);
}

// ---------------- GEMM + ghost BN + priors + pair-fused sparsemax ------------
// CTA tile 128x256, 256 threads, 8 warps, warp tile 64x64:
//   wm = wid&1 (row half), wn = wid>>1 (col quarter)
__global__ __launch_bounds__(256, 1) void gemm_bn_kernel(
    const float* __restrict__ A,
    const float* __restrict__ priors,
    const float* __restrict__ gamma,
    const float* __restrict__ beta,
    float* __restrict__ out)
{
    extern __shared__ char smem[];
    const uint32_t sb = smem_u32(smem);
    const int tid = threadIdx.x;
    const int lane = tid & 31;
    const int wid = tid >> 5;
    const int wm = wid & 1;       // rows wm*64..
    const int wn = wid >> 1;      // cols wn*64..
    const int col0 = blockIdx.x * 256;
    const int row0 = blockIdx.y * 128;

    float acc[4][8][4];
#pragma unroll
    for (int mi = 0; mi < 4; ++mi)
#pragma unroll
        for (int ni = 0; ni < 8; ++ni)
#pragma unroll
            for (int e = 0; e < 4; ++e) acc[mi][ni][e] = 0.f;

    const uint32_t a_off = (uint32_t)((lane & 15) * PITCH + (lane >> 4) * 16);
    const uint32_t b_off = (uint32_t)(((lane & 7) + 8 * ((lane >> 3) & 1)) * PITCH +
                                      (lane >> 4) * 16);

    float4 av[8];

    // ---- prologue: stage 0 ----
#pragma unroll
    for (int i = 0; i < 8; ++i) {
        int idx = tid + 256 * i;                 // 2048 float4 (A 128x64 fp32)
        av[i] = *(const float4*)&A[(size_t)(row0 + (idx >> 4)) * K_DIM + (idx & 15) * 4];
    }
#pragma unroll
    for (int i = 0; i < 8; ++i) {
        int idx = tid + 256 * i;                 // 2048 cp16 (B 256x64 fp16)
        int r = idx >> 3, ch = idx & 7;
        cp16(sb + B_OFF + r * PITCH + ch * 16,
             g_Wt + (size_t)(col0 + r) * K_DIM + ch * 8);
    }
    CP_COMMIT();
    {
        char* sp = smem;
#pragma unroll
        for (int i = 0; i < 8; ++i) {
            int idx = tid + 256 * i;
            int r = idx >> 4, c4 = idx & 15;
            float4 v = av[i];
            uint2 hp;
            hp.x = pack_f16(v.x, v.y);
            hp.y = pack_f16(v.z, v.w);
            *(uint2*)(sp + A_OFF + r * PITCH + c4 * 8) = hp;
        }
    }
    CP_WAIT0();
    __syncthreads();

    // ---- main loop ----
    for (int kt = 0; kt < NKT; ++kt) {
        const int buf = kt & 1;
        if (kt + 1 < NKT) {
            const int kn = kt + 1;
#pragma unroll
            for (int i = 0; i < 8; ++i) {
                int idx = tid + 256 * i;
                av[i] = *(const float4*)&A[(size_t)(row0 + (idx >> 4)) * K_DIM +
                                           kn * KC + (idx & 15) * 4];
            }
            const uint32_t db = sb + (buf ^ 1) * STAGE_SZ;
#pragma unroll
            for (int i = 0; i < 8; ++i) {
                int idx = tid + 256 * i;
                int r = idx >> 3, ch = idx & 7;
                cp16(db + B_OFF + r * PITCH + ch * 16,
                     g_Wt + (size_t)(col0 + r) * K_DIM + kn * KC + ch * 8);
            }
            CP_COMMIT();
        }

        // compute on stage buf: 4 k16 steps, warp tile 64x64
        {
            const uint32_t stg = sb + buf * STAGE_SZ;
            const uint32_t aB = stg + A_OFF + (wm * 64) * PITCH + a_off;
            const uint32_t bB = stg + B_OFF + (wn * 64) * PITCH + b_off;
#pragma unroll
            for (int ks = 0; ks < 4; ++ks) {
                uint32_t ah[4][4];
#pragma unroll
                for (int mi = 0; mi < 4; ++mi)
                    ldsm4(ah[mi][0], ah[mi][1], ah[mi][2], ah[mi][3],
                          aB + mi * 16 * PITCH + ks * 32);
#pragma unroll
                for (int nb = 0; nb < 4; ++nb) {
                    uint32_t bh[4];
                    ldsm4(bh[0], bh[1], bh[2], bh[3], bB + nb * 16 * PITCH + ks * 32);
#pragma unroll
                    for (int n8 = 0; n8 < 2; ++n8) {
#pragma unroll
                        for (int mi = 0; mi < 4; ++mi)
                            mma16816(acc[mi][nb * 2 + n8], ah[mi], bh[n8], bh[n8 + 2]);
                    }
                }
            }
        }

        if (kt + 1 < NKT) {
            char* sp = smem + (buf ^ 1) * STAGE_SZ;
#pragma unroll
            for (int i = 0; i < 8; ++i) {
                int idx = tid + 256 * i;
                int r = idx >> 4, c4 = idx & 15;
                float4 v = av[i];
                uint2 hp;
                hp.x = pack_f16(v.x, v.y);
                hp.y = pack_f16(v.z, v.w);
                *(uint2*)(sp + A_OFF + r * PITCH + c4 * 8) = hp;
            }
            CP_WAIT0();
        }
        __syncthreads();
    }

    // ---- epilogue: ghost BN over this CTA's 128 rows, then *priors ----
    // acc layout: row = row0 + wm*64 + mi*16 + (lane>>2) + 8*h
    //             col = col0 + wn*64 + ni*8 + 2*(lane&3) + e ; acc[mi][ni][2h+e]
    float* ssum = (float*)smem;                 // [256][17]
    float* ssq  = (float*)(smem + 17408);       // [256][17]
    const int slot = wm * 8 + (lane >> 2);      // 16 contributors per column
#pragma unroll
    for (int ni = 0; ni < 8; ++ni) {
#pragma unroll
        for (int e = 0; e < 2; ++e) {
            float s = 0.f, q = 0.f;
#pragma unroll
            for (int mi = 0; mi < 4; ++mi)
#pragma unroll
                for (int h = 0; h < 2; ++h) {
                    float v = acc[mi][ni][2 * h + e];
                    s += v; q += v * v;
                }
            int c = wn * 64 + ni * 8 + 2 * (lane & 3) + e;
            ssum[c * 17 + slot] = s;
            ssq [c * 17 + slot] = q;
        }
    }
    __syncthreads();

    float* scales = (float*)(smem + 34816);
    float* shifts = (float*)(smem + 35840);
    {
        const int c = tid;    // 256 threads == 256 columns
        float s = 0.f, q = 0.f;
#pragma unroll
        for (int t = 0; t < 16; ++t) { s += ssum[c * 17 + t]; q += ssq[c * 17 + t]; }
        float mean = s * (1.f / 128.f);
        float var = q * (1.f / 128.f) - mean * mean;
        if (var < 0.f) var = 0.f;
        float sc = gamma[col0 + c] * rsqrtf(var + BN_EPS);
        scales[c] = sc;
        shifts[c] = beta[col0 + c] - mean * sc;
    }
    __syncthreads();

#pragma unroll
    for (int mi = 0; mi < 4; ++mi)
#pragma unroll
        for (int h = 0; h < 2; ++h) {
            int r = row0 + wm * 64 + mi * 16 + (lane >> 2) + 8 * h;
#pragma unroll
            for (int ni = 0; ni < 8; ++ni) {
                int c = wn * 64 + ni * 8 + 2 * (lane & 3);
                float2 p = *(const float2*)&priors[(size_t)r * N_DIM + col0 + c];
                float2 o;
                o.x = fmaf(acc[mi][ni][2 * h + 0], scales[c], shifts[c]) * p.x;
                o.y = fmaf(acc[mi][ni][2 * h + 1], scales[c + 1], shifts[c + 1]) * p.y;
                *(float2*)&out[(size_t)r * N_DIM + col0 + c] = o;
            }
        }

    // ---- pair rendezvous: both CTAs of this row-block, then split sparsemax --
    __threadfence();                  // publish z writes
    __syncthreads();
    if (tid == 0) {
        int prev = atomicAdd(&g_ctr[blockIdx.y], 1);
        if (prev == 0) {
            // first arriver: wait for peer, and atomically reset for next launch
            while (atomicCAS(&g_ctr[blockIdx.y], 2, 0) != 2) __nanosleep(40);
        }
        // second arriver (prev==1): peer already published; proceed
    }
    __syncthreads();
    __threadfence();                  // acquire peer's writes

    // this CTA sparsemaxes its own 64 rows (L2-hot): 8 warps x 8 rows
#pragma unroll 1
    for (int rr = 0; rr < 8; ++rr) {
        const int r = row0 + blockIdx.x * 64 + wid * 8 + rr;
        sparsemax_row(out + (size_t)r * N_DIM, lane);
    }
}

// ---------------------------------------------------------------------------
extern "C" void kernel_launch(void* const* d_in, const int* in_sizes, int n_in,
                              void* d_out, int out_size)
{
    const float* inputs = (const float*)d_in[0];   // [65536, 512]
    const float* priors = (const float*)d_in[1];   // [65536, 512]
    const float* Wm     = (const float*)d_in[2];   // [512, 512]
    const float* gamma  = (const float*)d_in[3];   // [512]
    const float* beta   = (const float*)d_in[4];   // [512]
    float* out = (float*)d_out;

    const int M = in_sizes[0] / K_DIM;             // 65536

    cudaFuncSetAttribute(gemm_bn_kernel, cudaFuncAttributeMaxDynamicSharedMemorySize,
                         SMEM_TOTAL);

    wconv_kernel<<<1024, 256>>>(Wm);
    gemm_bn_kernel<<<dim3(N_DIM / 256, M / 128), 256, SMEM_TOTAL>>>(
        inputs, priors, gamma, beta, out);
}

// round 14
// speedup vs baseline: 1.0038x; 1.0038x over previous
#include <cuda_runtime.h>
#include <cuda_fp16.h>
#include <cstdint>

#define K_DIM 512
#define N_DIM 512
#define BN_EPS 1e-3f
#define KC 64
#define NKT 8              // 512/64 k-chunks
#define PITCH 144          // smem row pitch bytes (64 fp16 = 128B + 16B pad)
#define A_OFF 0
#define B_OFF 18432        // A: 128 rows * 144B
#define STAGE_SZ 55296     // + B: 256 rows * 144B
#define SMEM_TOTAL (2 * STAGE_SZ)

// precomputed W (fp16), transposed to [n][k]
__device__ __align__(16) __half g_Wt[N_DIM * K_DIM];
// per-rowblock rendezvous counters (zero at start; self-reset via CAS each run)
__device__ int g_ctr[512];

// ---------------- helpers ---------------------------------------------------
__device__ __forceinline__ uint32_t smem_u32(const void* p) {
    uint32_t a;
    asm("{ .reg .u64 t; cvta.to.shared.u64 t, %1; cvt.u32.u64 %0, t; }" : "=r"(a) : "l"(p));
    return a;
}
__device__ __forceinline__ void cp16(uint32_t dst, const void* src) {
    asm volatile("cp.async.cg.shared.global [%0], [%1], 16;" :: "r"(dst), "l"(src));
}
#define CP_COMMIT() asm volatile("cp.async.commit_group;" ::: "memory")
#define CP_WAIT0()  asm volatile("cp.async.wait_group 0;" ::: "memory")

__device__ __forceinline__ void ldsm4(uint32_t& r0, uint32_t& r1, uint32_t& r2, uint32_t& r3,
                                      uint32_t a) {
    asm volatile("ldmatrix.sync.aligned.m8n8.x4.shared.b16 {%0,%1,%2,%3}, [%4];"
                 : "=r"(r0), "=r"(r1), "=r"(r2), "=r"(r3) : "r"(a));
}
__device__ __forceinline__ void mma16816(float* d, const uint32_t* a, uint32_t b0, uint32_t b1) {
    asm volatile("mma.sync.aligned.m16n8k16.row.col.f32.f16.f16.f32 "
                 "{%0,%1,%2,%3}, {%4,%5,%6,%7}, {%8,%9}, {%0,%1,%2,%3};"
                 : "+f"(d[0]), "+f"(d[1]), "+f"(d[2]), "+f"(d[3])
                 : "r"(a[0]), "r"(a[1]), "r"(a[2]), "r"(a[3]), "r"(b0), "r"(b1));
}
__device__ __forceinline__ uint32_t pack_f16(float x, float y) {
    return (uint32_t)__half_as_ushort(__float2half_rn(x)) |
           ((uint32_t)__half_as_ushort(__float2half_rn(y)) << 16);
}

__device__ __forceinline__ float wsumf(float v) {
#pragma unroll
    for (int o = 16; o > 0; o >>= 1) v += __shfl_xor_sync(0xffffffffu, v, o);
    return v;
}
__device__ __forceinline__ int wsumi(int v) {
#pragma unroll
    for (int o = 16; o > 0; o >>= 1) v += __shfl_xor_sync(0xffffffffu, v, o);
    return v;
}

// row-wise sparsemax (Michelot fixed point), one warp, 512 elems, in-place
__device__ __forceinline__ void sparsemax_row(float* __restrict__ row, int lane) {
    float z[16];
#pragma unroll
    for (int j = 0; j < 4; ++j) {
        const float4 v = *(const float4*)&row[lane * 4 + j * 128];
        z[j * 4 + 0] = v.x; z[j * 4 + 1] = v.y; z[j * 4 + 2] = v.z; z[j * 4 + 3] = v.w;
    }
    float s = 0.f;
#pragma unroll
    for (int i = 0; i < 16; ++i) s += z[i];
    s = wsumf(s);
    int cnt = N_DIM;
    float tau = (s - 1.0f) * (1.0f / N_DIM);
#pragma unroll 1
    for (int it = 0; it < 64; ++it) {
        float s2 = 0.f; int c2 = 0;
#pragma unroll
        for (int i = 0; i < 16; ++i)
            if (z[i] > tau) { s2 += z[i]; c2++; }
        s2 = wsumf(s2);
        c2 = wsumi(c2);
        if (c2 <= 0) break;
        const float ntau = (s2 - 1.0f) / (float)c2;
        if (c2 >= cnt) { tau = ntau; break; }
        cnt = c2;
        tau = ntau;
    }
#pragma unroll
    for (int j = 0; j < 4; ++j) {
        float4 o;
        o.x = fmaxf(z[j * 4 + 0] - tau, 0.f);
        o.y = fmaxf(z[j * 4 + 1] - tau, 0.f);
        o.z = fmaxf(z[j * 4 + 2] - tau, 0.f);
        o.w = fmaxf(z[j * 4 + 3] - tau, 0.f);
        *(float4*)&row[lane * 4 + j * 128] = o;
    }
}

// ---------------- W convert/transpose ---------------------------------------
__global__ void wconv_kernel(const float* __restrict__ W) {
    int idx = blockIdx.x * 256 + threadIdx.x;   // 1024 x 256 = 512*512
    int k = idx >> 9, n = idx & 511;
    g_Wt[n * K_DIM + k] = __float2half_rn(W[idx]);
}

// ---------------- GEMM + ghost BN + priors + pair-fused sparsemax ------------
// CTA tile 128x256, 256 threads, 8 warps, warp tile 64x64:
//   wm = wid&1 (row half), wn = wid>>1 (col quarter)
__global__ __launch_bounds__(256, 1) void gemm_bn_kernel(
    const float* __restrict__ A,
    const float* __restrict__ priors,
    const float* __restrict__ gamma,
    const float* __restrict__ beta,
    float* __restrict__ out)
{
    extern __shared__ char smem[];
    const uint32_t sb = smem_u32(smem);
    const int tid = threadIdx.x;
    const int lane = tid & 31;
    const int wid = tid >> 5;
    const int wm = wid & 1;       // rows wm*64..
    const int wn = wid >> 1;      // cols wn*64..
    const int col0 = blockIdx.x * 256;
    const int row0 = blockIdx.y * 128;

    float acc[4][8][4];
#pragma unroll
    for (int mi = 0; mi < 4; ++mi)
#pragma unroll
        for (int ni = 0; ni < 8; ++ni)
#pragma unroll
            for (int e = 0; e < 4; ++e) acc[mi][ni][e] = 0.f;

    const uint32_t a_off = (uint32_t)((lane & 15) * PITCH + (lane >> 4) * 16);
    const uint32_t b_off = (uint32_t)(((lane & 7) + 8 * ((lane >> 3) & 1)) * PITCH +
                                      (lane >> 4) * 16);

    float4 av[8];

    // ---- prologue: stage 0 ----
#pragma unroll
    for (int i = 0; i < 8; ++i) {
        int idx = tid + 256 * i;                 // 2048 float4 (A 128x64 fp32)
        av[i] = *(const float4*)&A[(size_t)(row0 + (idx >> 4)) * K_DIM + (idx & 15) * 4];
    }
#pragma unroll
    for (int i = 0; i < 8; ++i) {
        int idx = tid + 256 * i;                 // 2048 cp16 (B 256x64 fp16)
        int r = idx >> 3, ch = idx & 7;
        cp16(sb + B_OFF + r * PITCH + ch * 16,
             g_Wt + (size_t)(col0 + r) * K_DIM + ch * 8);
    }
    CP_COMMIT();
    {
        char* sp = smem;
#pragma unroll
        for (int i = 0; i < 8; ++i) {
            int idx = tid + 256 * i;
            int r = idx >> 4, c4 = idx & 15;
            float4 v = av[i];
            uint2 hp;
            hp.x = pack_f16(v.x, v.y);
            hp.y = pack_f16(v.z, v.w);
            *(uint2*)(sp + A_OFF + r * PITCH + c4 * 8) = hp;
        }
    }
    CP_WAIT0();
    __syncthreads();

    // ---- main loop ----
    for (int kt = 0; kt < NKT; ++kt) {
        const int buf = kt & 1;
        if (kt + 1 < NKT) {
            const int kn = kt + 1;
#pragma unroll
            for (int i = 0; i < 8; ++i) {
                int idx = tid + 256 * i;
                av[i] = *(const float4*)&A[(size_t)(row0 + (idx >> 4)) * K_DIM +
                                           kn * KC + (idx & 15) * 4];
            }
            const uint32_t db = sb + (buf ^ 1) * STAGE_SZ;
#pragma unroll
            for (int i = 0; i < 8; ++i) {
                int idx = tid + 256 * i;
                int r = idx >> 3, ch = idx & 7;
                cp16(db + B_OFF + r * PITCH + ch * 16,
                     g_Wt + (size_t)(col0 + r) * K_DIM + kn * KC + ch * 8);
            }
            CP_COMMIT();
        }

        // compute on stage buf: 4 k16 steps, warp tile 64x64
        {
            const uint32_t stg = sb + buf * STAGE_SZ;
            const uint32_t aB = stg + A_OFF + (wm * 64) * PITCH + a_off;
            const uint32_t bB = stg + B_OFF + (wn * 64) * PITCH + b_off;
#pragma unroll
            for (int ks = 0; ks < 4; ++ks) {
                uint32_t ah[4][4];
#pragma unroll
                for (int mi = 0; mi < 4; ++mi)
                    ldsm4(ah[mi][0], ah[mi][1], ah[mi][2], ah[mi][3],
                          aB + mi * 16 * PITCH + ks * 32);
#pragma unroll
                for (int nb = 0; nb < 4; ++nb) {
                    uint32_t bh[4];
                    ldsm4(bh[0], bh[1], bh[2], bh[3], bB + nb * 16 * PITCH + ks * 32);
#pragma unroll
                    for (int n8 = 0; n8 < 2; ++n8) {
#pragma unroll
                        for (int mi = 0; mi < 4; ++mi)
                            mma16816(acc[mi][nb * 2 + n8], ah[mi], bh[n8], bh[n8 + 2]);
                    }
                }
            }
        }

        if (kt + 1 < NKT) {
            char* sp = smem + (buf ^ 1) * STAGE_SZ;
#pragma unroll
            for (int i = 0; i < 8; ++i) {
                int idx = tid + 256 * i;
                int r = idx >> 4, c4 = idx & 15;
                float4 v = av[i];
                uint2 hp;
                hp.x = pack_f16(v.x, v.y);
                hp.y = pack_f16(v.z, v.w);
                *(uint2*)(sp + A_OFF + r * PITCH + c4 * 8) = hp;
            }
            CP_WAIT0();
        }
        __syncthreads();
    }

    // ---- epilogue: ghost BN over this CTA's 128 rows, then *priors ----
    // acc layout: row = row0 + wm*64 + mi*16 + (lane>>2) + 8*h
    //             col = col0 + wn*64 + ni*8 + 2*(lane&3) + e ; acc[mi][ni][2h+e]
    float* ssum = (float*)smem;                 // [256][17]
    float* ssq  = (float*)(smem + 17408);       // [256][17]
    const int slot = wm * 8 + (lane >> 2);      // 16 contributors per column
#pragma unroll
    for (int ni = 0; ni < 8; ++ni) {
#pragma unroll
        for (int e = 0; e < 2; ++e) {
            float s = 0.f, q = 0.f;
#pragma unroll
            for (int mi = 0; mi < 4; ++mi)
#pragma unroll
                for (int h = 0; h < 2; ++h) {
                    float v = acc[mi][ni][2 * h + e];
                    s += v; q += v * v;
                }
            int c = wn * 64 + ni * 8 + 2 * (lane & 3) + e;
            ssum[c * 17 + slot] = s;
            ssq [c * 17 + slot] = q;
        }
    }
    __syncthreads();

    float* scales = (float*)(smem + 34816);
    float* shifts = (float*)(smem + 35840);
    {
        const int c = tid;    // 256 threads == 256 columns
        float s = 0.f, q = 0.f;
#pragma unroll
        for (int t = 0; t < 16; ++t) { s += ssum[c * 17 + t]; q += ssq[c * 17 + t]; }
        float mean = s * (1.f / 128.f);
        float var = q * (1.f / 128.f) - mean * mean;
        if (var < 0.f) var = 0.f;
        float sc = gamma[col0 + c] * rsqrtf(var + BN_EPS);
        scales[c] = sc;
        shifts[c] = beta[col0 + c] - mean * sc;
    }
    __syncthreads();

#pragma unroll
    for (int mi = 0; mi < 4; ++mi)
#pragma unroll
        for (int h = 0; h < 2; ++h) {
            int r = row0 + wm * 64 + mi * 16 + (lane >> 2) + 8 * h;
#pragma unroll
            for (int ni = 0; ni < 8; ++ni) {
                int c = wn * 64 + ni * 8 + 2 * (lane & 3);
                float2 p = *(const float2*)&priors[(size_t)r * N_DIM + col0 + c];
                float2 o;
                o.x = fmaf(acc[mi][ni][2 * h + 0], scales[c], shifts[c]) * p.x;
                o.y = fmaf(acc[mi][ni][2 * h + 1], scales[c + 1], shifts[c + 1]) * p.y;
                *(float2*)&out[(size_t)r * N_DIM + col0 + c] = o;
            }
        }

    // ---- pair rendezvous: both CTAs of this row-block, then split sparsemax --
    __threadfence();                  // publish z writes
    __syncthreads();
    if (tid == 0) {
        int prev = atomicAdd(&g_ctr[blockIdx.y], 1);
        if (prev == 0) {
            // first arriver: wait for peer, and atomically reset for next launch
            while (atomicCAS(&g_ctr[blockIdx.y], 2, 0) != 2) __nanosleep(40);
        }
        // second arriver (prev==1): peer already published; proceed
    }
    __syncthreads();
    __threadfence();                  // acquire peer's writes

    // this CTA sparsemaxes its own 64 rows (L2-hot): 8 warps x 8 rows
#pragma unroll 1
    for (int rr = 0; rr < 8; ++rr) {
        const int r = row0 + blockIdx.x * 64 + wid * 8 + rr;
        sparsemax_row(out + (size_t)r * N_DIM, lane);
    }
}

// ---------------------------------------------------------------------------
extern "C" void kernel_launch(void* const* d_in, const int* in_sizes, int n_in,
                              void* d_out, int out_size)
{
    const float* inputs = (const float*)d_in[0];   // [65536, 512]
    const float* priors = (const float*)d_in[1];   // [65536, 512]
    const float* Wm     = (const float*)d_in[2];   // [512, 512]
    const float* gamma  = (const float*)d_in[3];   // [512]
    const float* beta   = (const float*)d_in[4];   // [512]
    float* out = (float*)d_out;

    const int M = in_sizes[0] / K_DIM;             // 65536

    cudaFuncSetAttribute(gemm_bn_kernel, cudaFuncAttributeMaxDynamicSharedMemorySize,
                         SMEM_TOTAL);

    wconv_kernel<<<1024, 256>>>(Wm);
    gemm_bn_kernel<<<dim3(N_DIM / 256, M / 128), 256, SMEM_TOTAL>>>(
        inputs, priors, gamma, beta, out);
}

// round 15
// speedup vs baseline: 1.2968x; 1.2919x over previous
#include <cuda_runtime.h>
#include <cuda_fp16.h>
#include <cstdint>

#define K_DIM 512
#define N_DIM 512
#define BN_EPS 1e-3f
#define KC 64
#define NKT 8              // 512/64 k-chunks
#define PITCH 144          // smem row pitch bytes (64 fp16 = 128B + 16B pad)
#define A_OFF 0
#define B_OFF 18432        // A: 128 rows * 144B
#define STAGE_SZ 55296     // + B: 256 rows * 144B
#define SMEM_TOTAL (2 * STAGE_SZ)

// precomputed W (fp16), transposed to [n][k]
__device__ __align__(16) __half g_Wt[N_DIM * K_DIM];

// ---------------- helpers ---------------------------------------------------
__device__ __forceinline__ uint32_t smem_u32(const void* p) {
    uint32_t a;
    asm("{ .reg .u64 t; cvta.to.shared.u64 t, %1; cvt.u32.u64 %0, t; }" : "=r"(a) : "l"(p));
    return a;
}
__device__ __forceinline__ void cp16(uint32_t dst, const void* src) {
    asm volatile("cp.async.cg.shared.global [%0], [%1], 16;" :: "r"(dst), "l"(src));
}
#define CP_COMMIT() asm volatile("cp.async.commit_group;" ::: "memory")
#define CP_WAIT0()  asm volatile("cp.async.wait_group 0;" ::: "memory")

__device__ __forceinline__ void ldsm4(uint32_t& r0, uint32_t& r1, uint32_t& r2, uint32_t& r3,
                                      uint32_t a) {
    asm volatile("ldmatrix.sync.aligned.m8n8.x4.shared.b16 {%0,%1,%2,%3}, [%4];"
                 : "=r"(r0), "=r"(r1), "=r"(r2), "=r"(r3) : "r"(a));
}
__device__ __forceinline__ void mma16816(float* d, const uint32_t* a, uint32_t b0, uint32_t b1) {
    asm volatile("mma.sync.aligned.m16n8k16.row.col.f32.f16.f16.f32 "
                 "{%0,%1,%2,%3}, {%4,%5,%6,%7}, {%8,%9}, {%0,%1,%2,%3};"
                 : "+f"(d[0]), "+f"(d[1]), "+f"(d[2]), "+f"(d[3])
                 : "r"(a[0]), "r"(a[1]), "r"(a[2]), "r"(a[3]), "r"(b0), "r"(b1));
}
__device__ __forceinline__ uint32_t pack_f16(float x, float y) {
    return (uint32_t)__half_as_ushort(__float2half_rn(x)) |
           ((uint32_t)__half_as_ushort(__float2half_rn(y)) << 16);
}

// ---------------- W convert/transpose ---------------------------------------
__global__ void wconv_kernel(const float* __restrict__ W) {
    int idx = blockIdx.x * 256 + threadIdx.x;   // 1024 x 256 = 512*512
    int k = idx >> 9, n = idx & 511;
    g_Wt[n * K_DIM + k] = __float2half_rn(W[idx]);
}

// ---------------- GEMM (fp16 1-pass HMMA) + ghost BN + priors ----------------
// CTA tile 128x256, 256 threads, 8 warps, warp tile 64x64:
//   wm = wid&1 (row half), wn = wid>>1 (col quarter)
__global__ __launch_bounds__(256, 1) void gemm_bn_kernel(
    const float* __restrict__ A,
    const float* __restrict__ priors,
    const float* __restrict__ gamma,
    const float* __restrict__ beta,
    float* __restrict__ out)
{
    extern __shared__ char smem[];
    const uint32_t sb = smem_u32(smem);
    const int tid = threadIdx.x;
    const int lane = tid & 31;
    const int wid = tid >> 5;
    const int wm = wid & 1;       // rows wm*64..
    const int wn = wid >> 1;      // cols wn*64..
    const int col0 = blockIdx.x * 256;
    const int row0 = blockIdx.y * 128;

    float acc[4][8][4];
#pragma unroll
    for (int mi = 0; mi < 4; ++mi)
#pragma unroll
        for (int ni = 0; ni < 8; ++ni)
#pragma unroll
            for (int e = 0; e < 4; ++e) acc[mi][ni][e] = 0.f;

    const uint32_t a_off = (uint32_t)((lane & 15) * PITCH + (lane >> 4) * 16);
    const uint32_t b_off = (uint32_t)(((lane & 7) + 8 * ((lane >> 3) & 1)) * PITCH +
                                      (lane >> 4) * 16);

    float4 av[8];

    // ---- prologue: stage 0 ----
#pragma unroll
    for (int i = 0; i < 8; ++i) {
        int idx = tid + 256 * i;                 // 2048 float4 (A 128x64 fp32)
        av[i] = *(const float4*)&A[(size_t)(row0 + (idx >> 4)) * K_DIM + (idx & 15) * 4];
    }
#pragma unroll
    for (int i = 0; i < 8; ++i) {
        int idx = tid + 256 * i;                 // 2048 cp16 (B 256x64 fp16)
        int r = idx >> 3, ch = idx & 7;
        cp16(sb + B_OFF + r * PITCH + ch * 16,
             g_Wt + (size_t)(col0 + r) * K_DIM + ch * 8);
    }
    CP_COMMIT();
    {
        char* sp = smem;
#pragma unroll
        for (int i = 0; i < 8; ++i) {
            int idx = tid + 256 * i;
            int r = idx >> 4, c4 = idx & 15;
            float4 v = av[i];
            uint2 hp;
            hp.x = pack_f16(v.x, v.y);
            hp.y = pack_f16(v.z, v.w);
            *(uint2*)(sp + A_OFF + r * PITCH + c4 * 8) = hp;
        }
    }
    CP_WAIT0();
    __syncthreads();

    // ---- main loop ----
    for (int kt = 0; kt < NKT; ++kt) {
        const int buf = kt & 1;
        if (kt + 1 < NKT) {
            const int kn = kt + 1;
#pragma unroll
            for (int i = 0; i < 8; ++i) {
                int idx = tid + 256 * i;
                av[i] = *(const float4*)&A[(size_t)(row0 + (idx >> 4)) * K_DIM +
                                           kn * KC + (idx & 15) * 4];
            }
            const uint32_t db = sb + (buf ^ 1) * STAGE_SZ;
#pragma unroll
            for (int i = 0; i < 8; ++i) {
                int idx = tid + 256 * i;
                int r = idx >> 3, ch = idx & 7;
                cp16(db + B_OFF + r * PITCH + ch * 16,
                     g_Wt + (size_t)(col0 + r) * K_DIM + kn * KC + ch * 8);
            }
            CP_COMMIT();
        }

        // compute on stage buf: 4 k16 steps, warp tile 64x64
        {
            const uint32_t stg = sb + buf * STAGE_SZ;
            const uint32_t aB = stg + A_OFF + (wm * 64) * PITCH + a_off;
            const uint32_t bB = stg + B_OFF + (wn * 64) * PITCH + b_off;
#pragma unroll
            for (int ks = 0; ks < 4; ++ks) {
                uint32_t ah[4][4];
#pragma unroll
                for (int mi = 0; mi < 4; ++mi)
                    ldsm4(ah[mi][0], ah[mi][1], ah[mi][2], ah[mi][3],
                          aB + mi * 16 * PITCH + ks * 32);
#pragma unroll
                for (int nb = 0; nb < 4; ++nb) {
                    uint32_t bh[4];
                    ldsm4(bh[0], bh[1], bh[2], bh[3], bB + nb * 16 * PITCH + ks * 32);
#pragma unroll
                    for (int n8 = 0; n8 < 2; ++n8) {
#pragma unroll
                        for (int mi = 0; mi < 4; ++mi)
                            mma16816(acc[mi][nb * 2 + n8], ah[mi], bh[n8], bh[n8 + 2]);
                    }
                }
            }
        }

        if (kt + 1 < NKT) {
            char* sp = smem + (buf ^ 1) * STAGE_SZ;
#pragma unroll
            for (int i = 0; i < 8; ++i) {
                int idx = tid + 256 * i;
                int r = idx >> 4, c4 = idx & 15;
                float4 v = av[i];
                uint2 hp;
                hp.x = pack_f16(v.x, v.y);
                hp.y = pack_f16(v.z, v.w);
                *(uint2*)(sp + A_OFF + r * PITCH + c4 * 8) = hp;
            }
            CP_WAIT0();
        }
        __syncthreads();
    }

    // ---- epilogue: ghost BN over this CTA's 128 rows, then *priors ----
    // acc layout: row = row0 + wm*64 + mi*16 + (lane>>2) + 8*h
    //             col = col0 + wn*64 + ni*8 + 2*(lane&3) + e ; acc[mi][ni][2h+e]
    float* ssum = (float*)smem;                 // [256][17]
    float* ssq  = (float*)(smem + 17408);       // [256][17]
    const int slot = wm * 8 + (lane >> 2);      // 16 contributors per column
#pragma unroll
    for (int ni = 0; ni < 8; ++ni) {
#pragma unroll
        for (int e = 0; e < 2; ++e) {
            float s = 0.f, q = 0.f;
#pragma unroll
            for (int mi = 0; mi < 4; ++mi)
#pragma unroll
                for (int h = 0; h < 2; ++h) {
                    float v = acc[mi][ni][2 * h + e];
                    s += v; q += v * v;
                }
            int c = wn * 64 + ni * 8 + 2 * (lane & 3) + e;
            ssum[c * 17 + slot] = s;
            ssq [c * 17 + slot] = q;
        }
    }
    __syncthreads();

    float* scales = (float*)(smem + 34816);
    float* shifts = (float*)(smem + 35840);
    {
        const int c = tid;    // 256 threads == 256 columns
        float s = 0.f, q = 0.f;
#pragma unroll
        for (int t = 0; t < 16; ++t) { s += ssum[c * 17 + t]; q += ssq[c * 17 + t]; }
        float mean = s * (1.f / 128.f);
        float var = q * (1.f / 128.f) - mean * mean;
        if (var < 0.f) var = 0.f;
        float sc = gamma[col0 + c] * rsqrtf(var + BN_EPS);
        scales[c] = sc;
        shifts[c] = beta[col0 + c] - mean * sc;
    }
    __syncthreads();

#pragma unroll
    for (int mi = 0; mi < 4; ++mi)
#pragma unroll
        for (int h = 0; h < 2; ++h) {
            int r = row0 + wm * 64 + mi * 16 + (lane >> 2) + 8 * h;
#pragma unroll
            for (int ni = 0; ni < 8; ++ni) {
                int c = wn * 64 + ni * 8 + 2 * (lane & 3);
                float2 p = *(const float2*)&priors[(size_t)r * N_DIM + col0 + c];
                float2 o;
                o.x = fmaf(acc[mi][ni][2 * h + 0], scales[c], shifts[c]) * p.x;
                o.y = fmaf(acc[mi][ni][2 * h + 1], scales[c + 1], shifts[c + 1]) * p.y;
                *(float2*)&out[(size_t)r * N_DIM + col0 + c] = o;
            }
        }
}

// ---------------- sparsemax (descending row order: harvest hot L2 tail) ------
__device__ __forceinline__ float wsumf(float v) {
#pragma unroll
    for (int o = 16; o > 0; o >>= 1) v += __shfl_xor_sync(0xffffffffu, v, o);
    return v;
}
__device__ __forceinline__ int wsumi(int v) {
#pragma unroll
    for (int o = 16; o > 0; o >>= 1) v += __shfl_xor_sync(0xffffffffu, v, o);
    return v;
}

__global__ __launch_bounds__(256) void sparsemax_kernel(float* __restrict__ u, int M)
{
    const int gwarp = (blockIdx.x * blockDim.x + threadIdx.x) >> 5;
    const int lane  = threadIdx.x & 31;
    if (gwarp >= M) return;
    // process rows in DESCENDING order: the GEMM wrote high rows last,
    // so they are the L2-resident ones when this kernel starts.
    float* row = u + (size_t)(M - 1 - gwarp) * N_DIM;

    float z[16];
#pragma unroll
    for (int j = 0; j < 4; ++j) {
        const float4 v = *(const float4*)&row[lane * 4 + j * 128];
        z[j * 4 + 0] = v.x; z[j * 4 + 1] = v.y; z[j * 4 + 2] = v.z; z[j * 4 + 3] = v.w;
    }

    // Michelot fixed point; first iteration uses the full set (tau = -inf)
    int   cnt = N_DIM + 1;           // sentinel > any achievable support
    float tau = -1e30f;

#pragma unroll 1
    for (int it = 0; it < 64; ++it) {
        float s2 = 0.f; int c2 = 0;
#pragma unroll
        for (int i = 0; i < 16; ++i)
            if (z[i] > tau) { s2 += z[i]; c2++; }
        s2 = wsumf(s2);
        c2 = wsumi(c2);
        if (c2 <= 0) break;
        const float ntau = (s2 - 1.0f) / (float)c2;
        if (c2 >= cnt) { tau = ntau; break; }
        cnt = c2;
        tau = ntau;
    }

#pragma unroll
    for (int j = 0; j < 4; ++j) {
        float4 o;
        o.x = fmaxf(z[j * 4 + 0] - tau, 0.f);
        o.y = fmaxf(z[j * 4 + 1] - tau, 0.f);
        o.z = fmaxf(z[j * 4 + 2] - tau, 0.f);
        o.w = fmaxf(z[j * 4 + 3] - tau, 0.f);
        *(float4*)&row[lane * 4 + j * 128] = o;
    }
}

// ---------------------------------------------------------------------------
extern "C" void kernel_launch(void* const* d_in, const int* in_sizes, int n_in,
                              void* d_out, int out_size)
{
    const float* inputs = (const float*)d_in[0];   // [65536, 512]
    const float* priors = (const float*)d_in[1];   // [65536, 512]
    const float* Wm     = (const float*)d_in[2];   // [512, 512]
    const float* gamma  = (const float*)d_in[3];   // [512]
    const float* beta   = (const float*)d_in[4];   // [512]
    float* out = (float*)d_out;

    const int M = in_sizes[0] / K_DIM;             // 65536

    cudaFuncSetAttribute(gemm_bn_kernel, cudaFuncAttributeMaxDynamicSharedMemorySize,
                         SMEM_TOTAL);

    wconv_kernel<<<1024, 256>>>(Wm);
    gemm_bn_kernel<<<dim3(N_DIM / 256, M / 128), 256, SMEM_TOTAL>>>(
        inputs, priors, gamma, beta, out);

    const int blocks = (M * 32 + 255) / 256;
    sparsemax_kernel<<<blocks, 256>>>(out, M);
}

// round 16
// speedup vs baseline: 1.4017x; 1.0809x over previous
#include <cuda_runtime.h>
#include <cuda_fp16.h>
#include <cstdint>

#define K_DIM 512
#define N_DIM 512
#define BN_EPS 1e-3f
#define KC 64
#define NKT 8              // 512/64 k-chunks
#define PITCH 144          // smem row pitch bytes (64 fp16 = 128B + 16B pad)
#define A_OFF 0
#define B_OFF 18432        // A: 128 rows * 144B
#define STAGE_SZ 55296     // + B: 256 rows * 144B
#define SMEM_TOTAL (2 * STAGE_SZ)

// precomputed W (fp16), transposed to [n][k]
__device__ __align__(16) __half g_Wt[N_DIM * K_DIM];

// ---------------- helpers ---------------------------------------------------
__device__ __forceinline__ uint32_t smem_u32(const void* p) {
    uint32_t a;
    asm("{ .reg .u64 t; cvta.to.shared.u64 t, %1; cvt.u32.u64 %0, t; }" : "=r"(a) : "l"(p));
    return a;
}
__device__ __forceinline__ void cp16(uint32_t dst, const void* src) {
    asm volatile("cp.async.cg.shared.global [%0], [%1], 16;" :: "r"(dst), "l"(src));
}
#define CP_COMMIT() asm volatile("cp.async.commit_group;" ::: "memory")
#define CP_WAIT0()  asm volatile("cp.async.wait_group 0;" ::: "memory")

__device__ __forceinline__ void ldsm4(uint32_t& r0, uint32_t& r1, uint32_t& r2, uint32_t& r3,
                                      uint32_t a) {
    asm volatile("ldmatrix.sync.aligned.m8n8.x4.shared.b16 {%0,%1,%2,%3}, [%4];"
                 : "=r"(r0), "=r"(r1), "=r"(r2), "=r"(r3) : "r"(a));
}
__device__ __forceinline__ void mma16816(float* d, const uint32_t* a, uint32_t b0, uint32_t b1) {
    asm volatile("mma.sync.aligned.m16n8k16.row.col.f32.f16.f16.f32 "
                 "{%0,%1,%2,%3}, {%4,%5,%6,%7}, {%8,%9}, {%0,%1,%2,%3};"
                 : "+f"(d[0]), "+f"(d[1]), "+f"(d[2]), "+f"(d[3])
                 : "r"(a[0]), "r"(a[1]), "r"(a[2]), "r"(a[3]), "r"(b0), "r"(b1));
}
__device__ __forceinline__ uint32_t pack_f16(float x, float y) {
    return (uint32_t)__half_as_ushort(__float2half_rn(x)) |
           ((uint32_t)__half_as_ushort(__float2half_rn(y)) << 16);
}

// ---------------- W convert/transpose ---------------------------------------
__global__ void wconv_kernel(const float* __restrict__ W) {
    int idx = blockIdx.x * 256 + threadIdx.x;   // 1024 x 256 = 512*512
    int k = idx >> 9, n = idx & 511;
    g_Wt[n * K_DIM + k] = __float2half_rn(W[idx]);
}

// ---------------- GEMM (fp16 1-pass HMMA) + ghost BN + priors ----------------
// CTA tile 128x256, 256 threads, 8 warps, warp tile 64x64:
//   wm = wid&1 (row half), wn = wid>>1 (col quarter)
__global__ __launch_bounds__(256, 1) void gemm_bn_kernel(
    const float* __restrict__ A,
    const float* __restrict__ priors,
    const float* __restrict__ gamma,
    const float* __restrict__ beta,
    float* __restrict__ out)
{
    extern __shared__ char smem[];
    const uint32_t sb = smem_u32(smem);
    const int tid = threadIdx.x;
    const int lane = tid & 31;
    const int wid = tid >> 5;
    const int wm = wid & 1;       // rows wm*64..
    const int wn = wid >> 1;      // cols wn*64..
    const int col0 = blockIdx.x * 256;
    const int row0 = blockIdx.y * 128;

    float acc[4][8][4];
#pragma unroll
    for (int mi = 0; mi < 4; ++mi)
#pragma unroll
        for (int ni = 0; ni < 8; ++ni)
#pragma unroll
            for (int e = 0; e < 4; ++e) acc[mi][ni][e] = 0.f;

    const uint32_t a_off = (uint32_t)((lane & 15) * PITCH + (lane >> 4) * 16);
    const uint32_t b_off = (uint32_t)(((lane & 7) + 8 * ((lane >> 3) & 1)) * PITCH +
                                      (lane >> 4) * 16);

    float4 av[8];

    // ---- prologue: stage 0 ----
#pragma unroll
    for (int i = 0; i < 8; ++i) {
        int idx = tid + 256 * i;                 // 2048 float4 (A 128x64 fp32)
        av[i] = *(const float4*)&A[(size_t)(row0 + (idx >> 4)) * K_DIM + (idx & 15) * 4];
    }
#pragma unroll
    for (int i = 0; i < 8; ++i) {
        int idx = tid + 256 * i;                 // 2048 cp16 (B 256x64 fp16)
        int r = idx >> 3, ch = idx & 7;
        cp16(sb + B_OFF + r * PITCH + ch * 16,
             g_Wt + (size_t)(col0 + r) * K_DIM + ch * 8);
    }
    CP_COMMIT();
    {
        char* sp = smem;
#pragma unroll
        for (int i = 0; i < 8; ++i) {
            int idx = tid + 256 * i;
            int r = idx >> 4, c4 = idx & 15;
            float4 v = av[i];
            uint2 hp;
            hp.x = pack_f16(v.x, v.y);
            hp.y = pack_f16(v.z, v.w);
            *(uint2*)(sp + A_OFF + r * PITCH + c4 * 8) = hp;
        }
    }
    CP_WAIT0();
    __syncthreads();

    // ---- main loop ----
    for (int kt = 0; kt < NKT; ++kt) {
        const int buf = kt & 1;
        if (kt + 1 < NKT) {
            const int kn = kt + 1;
#pragma unroll
            for (int i = 0; i < 8; ++i) {
                int idx = tid + 256 * i;
                av[i] = *(const float4*)&A[(size_t)(row0 + (idx >> 4)) * K_DIM +
                                           kn * KC + (idx & 15) * 4];
            }
            const uint32_t db = sb + (buf ^ 1) * STAGE_SZ;
#pragma unroll
            for (int i = 0; i < 8; ++i) {
                int idx = tid + 256 * i;
                int r = idx >> 3, ch = idx & 7;
                cp16(db + B_OFF + r * PITCH + ch * 16,
                     g_Wt + (size_t)(col0 + r) * K_DIM + kn * KC + ch * 8);
            }
            CP_COMMIT();
        }

        // compute on stage buf: 4 k16 steps, warp tile 64x64
        {
            const uint32_t stg = sb + buf * STAGE_SZ;
            const uint32_t aB = stg + A_OFF + (wm * 64) * PITCH + a_off;
            const uint32_t bB = stg + B_OFF + (wn * 64) * PITCH + b_off;
#pragma unroll
            for (int ks = 0; ks < 4; ++ks) {
                uint32_t ah[4][4];
#pragma unroll
                for (int mi = 0; mi < 4; ++mi)
                    ldsm4(ah[mi][0], ah[mi][1], ah[mi][2], ah[mi][3],
                          aB + mi * 16 * PITCH + ks * 32);
#pragma unroll
                for (int nb = 0; nb < 4; ++nb) {
                    uint32_t bh[4];
                    ldsm4(bh[0], bh[1], bh[2], bh[3], bB + nb * 16 * PITCH + ks * 32);
#pragma unroll
                    for (int n8 = 0; n8 < 2; ++n8) {
#pragma unroll
                        for (int mi = 0; mi < 4; ++mi)
                            mma16816(acc[mi][nb * 2 + n8], ah[mi], bh[n8], bh[n8 + 2]);
                    }
                }
            }
        }

        if (kt + 1 < NKT) {
            char* sp = smem + (buf ^ 1) * STAGE_SZ;
#pragma unroll
            for (int i = 0; i < 8; ++i) {
                int idx = tid + 256 * i;
                int r = idx >> 4, c4 = idx & 15;
                float4 v = av[i];
                uint2 hp;
                hp.x = pack_f16(v.x, v.y);
                hp.y = pack_f16(v.z, v.w);
                *(uint2*)(sp + A_OFF + r * PITCH + c4 * 8) = hp;
            }
            CP_WAIT0();
        }
        __syncthreads();
    }

    // ---- epilogue: ghost BN over this CTA's 128 rows, then *priors ----
    // acc layout: row = row0 + wm*64 + mi*16 + (lane>>2) + 8*h
    //             col = col0 + wn*64 + ni*8 + 2*(lane&3) + e ; acc[mi][ni][2h+e]
    float* ssum = (float*)smem;                 // [256][17]
    float* ssq  = (float*)(smem + 17408);       // [256][17]
    const int slot = wm * 8 + (lane >> 2);      // 16 contributors per column
#pragma unroll
    for (int ni = 0; ni < 8; ++ni) {
#pragma unroll
        for (int e = 0; e < 2; ++e) {
            float s = 0.f, q = 0.f;
#pragma unroll
            for (int mi = 0; mi < 4; ++mi)
#pragma unroll
                for (int h = 0; h < 2; ++h) {
                    float v = acc[mi][ni][2 * h + e];
                    s += v; q += v * v;
                }
            int c = wn * 64 + ni * 8 + 2 * (lane & 3) + e;
            ssum[c * 17 + slot] = s;
            ssq [c * 17 + slot] = q;
        }
    }
    __syncthreads();

    float* scales = (float*)(smem + 34816);
    float* shifts = (float*)(smem + 35840);
    {
        const int c = tid;    // 256 threads == 256 columns
        float s = 0.f, q = 0.f;
#pragma unroll
        for (int t = 0; t < 16; ++t) { s += ssum[c * 17 + t]; q += ssq[c * 17 + t]; }
        float mean = s * (1.f / 128.f);
        float var = q * (1.f / 128.f) - mean * mean;
        if (var < 0.f) var = 0.f;
        float sc = gamma[col0 + c] * rsqrtf(var + BN_EPS);
        scales[c] = sc;
        shifts[c] = beta[col0 + c] - mean * sc;
    }
    __syncthreads();

#pragma unroll
    for (int mi = 0; mi < 4; ++mi)
#pragma unroll
        for (int h = 0; h < 2; ++h) {
            int r = row0 + wm * 64 + mi * 16 + (lane >> 2) + 8 * h;
#pragma unroll
            for (int ni = 0; ni < 8; ++ni) {
                int c = wn * 64 + ni * 8 + 2 * (lane & 3);
                float2 p = *(const float2*)&priors[(size_t)r * N_DIM + col0 + c];
                float2 o;
                o.x = fmaf(acc[mi][ni][2 * h + 0], scales[c], shifts[c]) * p.x;
                o.y = fmaf(acc[mi][ni][2 * h + 1], scales[c + 1], shifts[c + 1]) * p.y;
                *(float2*)&out[(size_t)r * N_DIM + col0 + c] = o;
            }
        }
}

// ---------------- sparsemax (warm start tau0 = max-1; redux count) ----------
__device__ __forceinline__ float wsumf(float v) {
#pragma unroll
    for (int o = 16; o > 0; o >>= 1) v += __shfl_xor_sync(0xffffffffu, v, o);
    return v;
}
__device__ __forceinline__ float wmaxf(float v) {
#pragma unroll
    for (int o = 16; o > 0; o >>= 1) v = fmaxf(v, __shfl_xor_sync(0xffffffffu, v, o));
    return v;
}
__device__ __forceinline__ int wredux(int v) {
    int r;
    asm volatile("redux.sync.add.s32 %0, %1, 0xffffffff;" : "=r"(r) : "r"(v));
    return r;
}

__global__ __launch_bounds__(256) void sparsemax_kernel(float* __restrict__ u, int M)
{
    const int gwarp = (blockIdx.x * blockDim.x + threadIdx.x) >> 5;
    const int lane  = threadIdx.x & 31;
    if (gwarp >= M) return;
    float* row = u + (size_t)gwarp * N_DIM;

    float z[16];
#pragma unroll
    for (int j = 0; j < 4; ++j) {
        const float4 v = *(const float4*)&row[lane * 4 + j * 128];
        z[j * 4 + 0] = v.x; z[j * 4 + 1] = v.y; z[j * 4 + 2] = v.z; z[j * 4 + 3] = v.w;
    }

    // warm start: tau* in [max-1, max), so tau0 = max-1 is a valid Michelot
    // start (any tau <= tau* yields tau <= next <= tau*; supports shrink).
    float m = -1e30f;
#pragma unroll
    for (int i = 0; i < 16; ++i) m = fmaxf(m, z[i]);
    float tau = wmaxf(m) - 1.0f;

    int cnt = N_DIM + 1;      // sentinel > any achievable support size

#pragma unroll 1
    for (int it = 0; it < 64; ++it) {
        float s2 = 0.f; int c2 = 0;
#pragma unroll
        for (int i = 0; i < 16; ++i)
            if (z[i] > tau) { s2 += z[i]; c2++; }
        s2 = wsumf(s2);
        c2 = wredux(c2);
        if (c2 <= 0) break;
        const float ntau = (s2 - 1.0f) / (float)c2;
        if (c2 >= cnt) { tau = ntau; break; }
        cnt = c2;
        tau = ntau;
    }

#pragma unroll
    for (int j = 0; j < 4; ++j) {
        float4 o;
        o.x = fmaxf(z[j * 4 + 0] - tau, 0.f);
        o.y = fmaxf(z[j * 4 + 1] - tau, 0.f);
        o.z = fmaxf(z[j * 4 + 2] - tau, 0.f);
        o.w = fmaxf(z[j * 4 + 3] - tau, 0.f);
        *(float4*)&row[lane * 4 + j * 128] = o;
    }
}

// ---------------------------------------------------------------------------
extern "C" void kernel_launch(void* const* d_in, const int* in_sizes, int n_in,
                              void* d_out, int out_size)
{
    const float* inputs = (const float*)d_in[0];   // [65536, 512]
    const float* priors = (const float*)d_in[1];   // [65536, 512]
    const float* Wm     = (const float*)d_in[2];   // [512, 512]
    const float* gamma  = (const float*)d_in[3];   // [512]
    const float* beta   = (const float*)d_in[4];   // [512]
    float* out = (float*)d_out;

    const int M = in_sizes[0] / K_DIM;             // 65536

    cudaFuncSetAttribute(gemm_bn_kernel, cudaFuncAttributeMaxDynamicSharedMemorySize,
                         SMEM_TOTAL);

    wconv_kernel<<<1024, 256>>>(Wm);
    gemm_bn_kernel<<<dim3(N_DIM / 256, M / 128), 256, SMEM_TOTAL>>>(
        inputs, priors, gamma, beta, out);

    const int blocks = (M * 32 + 255) / 256;
    sparsemax_kernel<<<blocks, 256>>>(out, M);
}